// round 1
// baseline (speedup 1.0000x reference)
#include <cuda_runtime.h>

// MazeBrain: recurrent adaptive-LIF population, T=1200 steps, B=16, N=1024.
// One persistent CTA per batch; sparse spike-list recurrent gather; history
// window read back from the spikes output region.

#define T_STEPS 1200
#define BATCH   16
#define NN      1024
#define WHIST   1000
#define TPB     256      // each thread owns 4 consecutive neurons

__global__ void __launch_bounds__(TPB, 1)
mazebrain_kernel(const float* __restrict__ Iext,   // [T,B,N]
                 const float* __restrict__ W,      // [N,N] (pre j, post m)
                 float* __restrict__ out)          // [2,T,B,N]: spikes, potentials
{
    const int b   = blockIdx.x;
    const int tid = threadIdx.x;
    const int m0  = tid * 4;

    __shared__ int s_list[2][NN];
    __shared__ int s_cnt[2];

    if (tid == 0) { s_cnt[0] = 0; s_cnt[1] = 0; }
    __syncthreads();

    float v[4], adapt[4], thr[4], rsum[4];
    int   refr[4];
#pragma unroll
    for (int k = 0; k < 4; k++) {
        v[k] = -65.0f; adapt[k] = 0.0f; thr[k] = -55.0f; rsum[k] = 0.0f; refr[k] = 0;
    }

    float* __restrict__ spikes_out = out;
    float* __restrict__ pot_out    = out + (size_t)T_STEPS * BATCH * NN;

    const float* __restrict__ Wcol = W + m0;   // thread's 4 columns
    int cur = 0;

    for (int t = 0; t < T_STEPS; t++) {
        const size_t ob = ((size_t)t * BATCH + b) * NN + m0;

        // ---- recurrent gather: I = Iext + sum over spiking rows of W[j, m0..m0+3]
        float4 iv = *(const float4*)(Iext + ob);
        float a0 = iv.x, a1 = iv.y, a2 = iv.z, a3 = iv.w;

        const int cnt = s_cnt[cur];
        const int* __restrict__ lst = s_list[cur];
        int s = 0;
        for (; s + 4 <= cnt; s += 4) {
            int j0 = lst[s], j1 = lst[s + 1], j2 = lst[s + 2], j3 = lst[s + 3];
            float4 w0 = *(const float4*)(Wcol + (size_t)j0 * NN);
            float4 w1 = *(const float4*)(Wcol + (size_t)j1 * NN);
            float4 w2 = *(const float4*)(Wcol + (size_t)j2 * NN);
            float4 w3 = *(const float4*)(Wcol + (size_t)j3 * NN);
            a0 += w0.x + w1.x + w2.x + w3.x;
            a1 += w0.y + w1.y + w2.y + w3.y;
            a2 += w0.z + w1.z + w2.z + w3.z;
            a3 += w0.w + w1.w + w2.w + w3.w;
        }
        for (; s < cnt; s++) {
            int j = lst[s];
            float4 w0 = *(const float4*)(Wcol + (size_t)j * NN);
            a0 += w0.x; a1 += w0.y; a2 += w0.z; a3 += w0.w;
        }

        float Iin[4] = {a0, a1, a2, a3};

        // ---- neuron update (faithful order: integrate -> fire/reset -> adapt -> homeo)
        float spk[4], vout[4];
#pragma unroll
        for (int k = 0; k < 4; k++) {
            bool  active = (refr[k] <= 0);
            float v_int  = 0.9f * (v[k] + 65.0f) - 65.0f + Iin[k] - adapt[k];
            float v1     = active ? v_int : v[k];
            int   r1     = active ? refr[k] : (refr[k] - 1);
            bool  fired  = (v1 >= thr[k]);
            float sp     = fired ? 1.0f : 0.0f;
            float v2     = fired ? -70.0f : v1;
            v[k]    = v2;
            vout[k] = v2;
            spk[k]  = sp;
            adapt[k] = (fired ? (adapt[k] + 0.2f) : adapt[k]) * 0.95f;
            refr[k]  = fired ? 5 : r1;
        }

        // ---- write outputs (also serves as the firing-history ring buffer)
        *(float4*)(spikes_out + ob) = make_float4(spk[0], spk[1], spk[2], spk[3]);
        *(float4*)(pot_out    + ob) = make_float4(vout[0], vout[1], vout[2], vout[3]);

        // ---- homeostatic sliding-window rate
        float old0 = 0.f, old1 = 0.f, old2 = 0.f, old3 = 0.f;
        if (t >= WHIST) {
            const size_t hb = ((size_t)(t - WHIST) * BATCH + b) * NN + m0;
            float4 o = *(const float4*)(spikes_out + hb);
            old0 = o.x; old1 = o.y; old2 = o.z; old3 = o.w;
        }
        float olds[4] = {old0, old1, old2, old3};
#pragma unroll
        for (int k = 0; k < 4; k++)
            rsum[k] += spk[k] - olds[k];

        if (t + 1 >= WHIST) {
#pragma unroll
            for (int k = 0; k < 4; k++) {
                float ta = thr[k] + 0.001f * (rsum[k] * (1.0f / WHIST) - 0.01f);
                thr[k] = fminf(fmaxf(ta, 0.1f), 5.0f);
            }
        }

        // ---- build next step's spike list (ping-pong buffers, 2 syncs/step)
        const int nxt = cur ^ 1;
        __syncthreads();   // everyone finished reading s_list[cur]; s_cnt[nxt]==0 visible
#pragma unroll
        for (int k = 0; k < 4; k++) {
            if (spk[k] > 0.0f) {
                int pos = atomicAdd(&s_cnt[nxt], 1);
                s_list[nxt][pos] = m0 + k;
            }
        }
        __syncthreads();   // builds visible for next iteration
        if (tid == 0) s_cnt[cur] = 0;   // reused at t+2; ordered by t+1's first sync
        cur = nxt;
    }
}

extern "C" void kernel_launch(void* const* d_in, const int* in_sizes, int n_in,
                              void* d_out, int out_size)
{
    const float* input_current = (const float*)d_in[0];  // [T,B,N]
    const float* W_rec         = (const float*)d_in[1];  // [N,N]
    float* out                 = (float*)d_out;          // [2,T,B,N]
    (void)in_sizes; (void)n_in; (void)out_size;

    mazebrain_kernel<<<BATCH, TPB>>>(input_current, W_rec, out);
}